// round 15
// baseline (speedup 1.0000x reference)
#include <cuda_runtime.h>
#include <cstdint>
#include <math.h>

// Problem constants
#define TT 512
#define BB 8
#define DD 512
#define NN 64

typedef unsigned long long ull;

// Scratch (allocation-free rule: __device__ globals)
__device__ float g_k[TT * BB * DD];
__device__ float g_q[TT * BB * DD];
__device__ float g_wx[TT * BB * NN];     // W_x @ x + b
__device__ float g_alpha[TT * BB * NN];  // sigmoid(W_alpha @ x + b_alpha)
__device__ float g_c2[TT * BB * NN];     // (1 - alpha) * v   (recur -> scan)

// ---------------------------------------------------------------------------
// Fast tanh (MUFU ex2 + rcp; abs err ~1e-7) and f32x2 packed helpers
// ---------------------------------------------------------------------------
__device__ __forceinline__ float fast_tanh(float x) {
    float e;
    asm("ex2.approx.f32 %0, %1;" : "=f"(e) : "f"(x * 2.8853900817779268f));
    float r;
    asm("rcp.approx.f32 %0, %1;" : "=f"(r) : "f"(e + 1.0f));
    return fmaf(-2.0f, r, 1.0f);
}
__device__ __forceinline__ float warp_sum(float v) {
    v += __shfl_xor_sync(0xffffffffu, v, 16);
    v += __shfl_xor_sync(0xffffffffu, v, 8);
    v += __shfl_xor_sync(0xffffffffu, v, 4);
    v += __shfl_xor_sync(0xffffffffu, v, 2);
    v += __shfl_xor_sync(0xffffffffu, v, 1);
    return v;
}
__device__ __forceinline__ float dot4(const float4 a, const float4 b) {
    return fmaf(a.x, b.x, fmaf(a.y, b.y, fmaf(a.z, b.z, a.w * b.w)));
}
__device__ __forceinline__ ull pack2(float lo, float hi) {
    ull r;
    asm("mov.b64 %0, {%1, %2};" : "=l"(r) : "f"(lo), "f"(hi));
    return r;
}
__device__ __forceinline__ float2 unpack2(ull v) {
    float2 f;
    asm("mov.b64 {%0, %1}, %2;" : "=f"(f.x), "=f"(f.y) : "l"(v));
    return f;
}
__device__ __forceinline__ ull fma2(ull a, ull b, ull c) {
    ull d;
    asm("fma.rn.f32x2 %0, %1, %2, %3;" : "=l"(d) : "l"(a), "l"(b), "l"(c));
    return d;
}
__device__ __forceinline__ ull mul2(ull a, ull b) {
    ull d;
    asm("mul.rn.f32x2 %0, %1, %2;" : "=l"(d) : "l"(a), "l"(b));
    return d;
}

// ============================================================================
// Kernel 1: fused projection GEMM (unchanged — passing, ~116us)
// ============================================================================
#define PM 4096
#define PK 512
#define PN 1152
#define TBM 128
#define TBN 128
#define TBK 16

__global__ __launch_bounds__(256) void proj_kernel(
    const float* __restrict__ x,
    const float* __restrict__ Wk, const float* __restrict__ Wq,
    const float* __restrict__ Wx, const float* __restrict__ Wa,
    const float* __restrict__ bvec, const float* __restrict__ ba)
{
    __shared__ float As[TBK][TBM + 4];
    __shared__ float Bs[TBK][TBN + 4];

    const int tid = threadIdx.x;
    const int tx = tid & 15;
    const int ty = tid >> 4;
    const int m0 = blockIdx.x * TBM;
    const int n0 = blockIdx.y * TBN;

    const int kq = tid & 3;
    const int r0 = tid >> 2;

    const float* wr0p;
    const float* wr1p;
    {
        int jg = n0 + r0;
        wr0p = (jg < 512) ? Wk + (size_t)jg * 512
             : (jg < 1024) ? Wq + (size_t)(jg - 512) * 512
             : (jg < 1088) ? Wx + (size_t)(jg - 1024) * 512
                           : Wa + (size_t)(jg - 1088) * 512;
        jg = n0 + r0 + 64;
        wr1p = (jg < 512) ? Wk + (size_t)jg * 512
             : (jg < 1024) ? Wq + (size_t)(jg - 512) * 512
             : (jg < 1088) ? Wx + (size_t)(jg - 1024) * 512
                           : Wa + (size_t)(jg - 1088) * 512;
    }
    const float* xr0 = x + (size_t)(m0 + r0) * PK;
    const float* xr1 = x + (size_t)(m0 + r0 + 64) * PK;

    float acc[8][8];
#pragma unroll
    for (int i = 0; i < 8; i++)
#pragma unroll
        for (int j = 0; j < 8; j++) acc[i][j] = 0.0f;

    for (int kt = 0; kt < PK; kt += TBK) {
        float4 a0 = *(const float4*)(xr0 + kt + kq * 4);
        float4 a1 = *(const float4*)(xr1 + kt + kq * 4);
        float4 b0 = *(const float4*)(wr0p + kt + kq * 4);
        float4 b1 = *(const float4*)(wr1p + kt + kq * 4);

        As[kq * 4 + 0][r0] = a0.x; As[kq * 4 + 1][r0] = a0.y;
        As[kq * 4 + 2][r0] = a0.z; As[kq * 4 + 3][r0] = a0.w;
        As[kq * 4 + 0][r0 + 64] = a1.x; As[kq * 4 + 1][r0 + 64] = a1.y;
        As[kq * 4 + 2][r0 + 64] = a1.z; As[kq * 4 + 3][r0 + 64] = a1.w;

        Bs[kq * 4 + 0][r0] = b0.x; Bs[kq * 4 + 1][r0] = b0.y;
        Bs[kq * 4 + 2][r0] = b0.z; Bs[kq * 4 + 3][r0] = b0.w;
        Bs[kq * 4 + 0][r0 + 64] = b1.x; Bs[kq * 4 + 1][r0 + 64] = b1.y;
        Bs[kq * 4 + 2][r0 + 64] = b1.z; Bs[kq * 4 + 3][r0 + 64] = b1.w;

        __syncthreads();

#pragma unroll
        for (int kk = 0; kk < TBK; kk++) {
            float a[8], bq[8];
            *(float4*)&a[0]  = *(const float4*)&As[kk][ty * 8];
            *(float4*)&a[4]  = *(const float4*)&As[kk][ty * 8 + 4];
            *(float4*)&bq[0] = *(const float4*)&Bs[kk][tx * 8];
            *(float4*)&bq[4] = *(const float4*)&Bs[kk][tx * 8 + 4];
#pragma unroll
            for (int i = 0; i < 8; i++)
#pragma unroll
                for (int j = 0; j < 8; j++)
                    acc[i][j] = fmaf(a[i], bq[j], acc[i][j]);
        }
        __syncthreads();
    }

    const int c0 = n0 + tx * 8;
    if (c0 < 512) {
#pragma unroll
        for (int i = 0; i < 8; i++) {
            int r = m0 + ty * 8 + i;
            float* base = g_k + (size_t)r * DD + c0;
            *(float4*)(base)     = make_float4(acc[i][0], acc[i][1], acc[i][2], acc[i][3]);
            *(float4*)(base + 4) = make_float4(acc[i][4], acc[i][5], acc[i][6], acc[i][7]);
        }
    } else if (c0 < 1024) {
#pragma unroll
        for (int i = 0; i < 8; i++) {
            int r = m0 + ty * 8 + i;
            float* base = g_q + (size_t)r * DD + (c0 - 512);
            *(float4*)(base)     = make_float4(acc[i][0], acc[i][1], acc[i][2], acc[i][3]);
            *(float4*)(base + 4) = make_float4(acc[i][4], acc[i][5], acc[i][6], acc[i][7]);
        }
    } else if (c0 < 1088) {
        const int cc = c0 - 1024;
        float bb[8];
#pragma unroll
        for (int j = 0; j < 8; j++) bb[j] = bvec[cc + j];
#pragma unroll
        for (int i = 0; i < 8; i++) {
            int r = m0 + ty * 8 + i;
            float* base = g_wx + (size_t)r * NN + cc;
#pragma unroll
            for (int j = 0; j < 8; j++) base[j] = acc[i][j] + bb[j];
        }
    } else {
        const int cc = c0 - 1088;
        float bb[8];
#pragma unroll
        for (int j = 0; j < 8; j++) bb[j] = ba[cc + j];
#pragma unroll
        for (int i = 0; i < 8; i++) {
            int r = m0 + ty * 8 + i;
            float* base = g_alpha + (size_t)r * NN + cc;
#pragma unroll
            for (int j = 0; j < 8; j++)
                base[j] = 1.0f / (1.0f + expf(-(acc[i][j] + bb[j])));
        }
    }
}

// ============================================================================
// Kernel 2: serial recurrence — one CTA per batch, NO inter-SM traffic.
// 512 threads: warp w owns rows 4w..4w+3; lane owns d in [16*lane, +16).
// S lives packed (f32x2) in registers; fused update+dot uses fma.rn.f32x2.
// Per step: r->rbuf, syncthreads, v-matvec (8-lane groups, 3-shfl), c2 out,
// packed update+dot, 4 interleaved butterflies. k staged via cp.async (3-buf).
// Emits only c2[t,b,n]; S/y are replayed by the parallel scan kernel.
// ============================================================================
__global__ void __launch_bounds__(512, 1)
recur_kernel(const float* __restrict__ S0, const float* __restrict__ Wr)
{
    const int b    = blockIdx.x;
    const int tid  = threadIdx.x;
    const int w    = tid >> 5;           // 0..15
    const int lane = tid & 31;
    const int grp  = lane >> 3;          // 0..3
    const int gl   = lane & 7;
    const int nv   = w * 4 + grp;        // row this lane reduces v for
    const int m0   = gl * 8;

    __shared__ float rbuf[2][NN];
    __shared__ __align__(16) float ksm[3][DD];

    // W_r fragment for v-matvec
    const float4 wrA = *(const float4*)(Wr + nv * NN + m0);
    const float4 wrB = *(const float4*)(Wr + nv * NN + m0 + 4);

    // S packed: 4 rows x 8 f32x2
    ull s2[4][8];
#pragma unroll
    for (int i = 0; i < 4; i++) {
        const ulonglong2* p = (const ulonglong2*)(S0 + (size_t)(b * NN + w * 4 + i) * DD + lane * 16);
#pragma unroll
        for (int c = 0; c < 4; c++) {
            ulonglong2 v = p[c];
            s2[i][2 * c]     = v.x;
            s2[i][2 * c + 1] = v.y;
        }
    }

    // Stage k(0) -> ksm[0], k(1) -> ksm[1]
    if (w < 4) {
        uint32_t d0 = (uint32_t)__cvta_generic_to_shared(&ksm[0][w * 128 + lane * 4]);
        uint32_t d1 = (uint32_t)__cvta_generic_to_shared(&ksm[1][w * 128 + lane * 4]);
        const float* s0p = g_k + (size_t)b * DD + w * 128 + lane * 4;
        const float* s1p = g_k + (size_t)BB * DD + (size_t)b * DD + w * 128 + lane * 4;
        asm volatile("cp.async.cg.shared.global [%0], [%1], 16;" :: "r"(d0), "l"(s0p) : "memory");
        asm volatile("cp.async.cg.shared.global [%0], [%1], 16;" :: "r"(d1), "l"(s1p) : "memory");
        asm volatile("cp.async.commit_group;" ::: "memory");
        asm volatile("cp.async.wait_group 0;" ::: "memory");
    }
    __syncthreads();

    // A_i(0) = S0 . k(0)
    float A0, A1, A2, A3;
    {
        const ull* kt = (const ull*)&ksm[0][lane * 16];
        ull a0 = 0ull, a1 = 0ull, a2 = 0ull, a3 = 0ull;
#pragma unroll
        for (int c = 0; c < 8; c++) {
            ull k2c = kt[c];
            a0 = fma2(s2[0][c], k2c, a0);
            a1 = fma2(s2[1][c], k2c, a1);
            a2 = fma2(s2[2][c], k2c, a2);
            a3 = fma2(s2[3][c], k2c, a3);
        }
        float2 f0 = unpack2(a0), f1 = unpack2(a1), f2 = unpack2(a2), f3 = unpack2(a3);
        float t0 = f0.x + f0.y, t1 = f1.x + f1.y, t2 = f2.x + f2.y, t3 = f3.x + f3.y;
#pragma unroll
        for (int off = 16; off >= 1; off >>= 1) {
            t0 += __shfl_xor_sync(0xffffffffu, t0, off);
            t1 += __shfl_xor_sync(0xffffffffu, t1, off);
            t2 += __shfl_xor_sync(0xffffffffu, t2, off);
            t3 += __shfl_xor_sync(0xffffffffu, t3, off);
        }
        A0 = t0; A1 = t1; A2 = t2; A3 = t3;
    }

    float wxc = __ldg(g_wx + b * NN + nv);
    float alc = __ldg(g_alpha + b * NN + nv);

    for (int t = 0; t < TT; t++) {
        const int ib = t & 1;

        // 1. r = tanh(A) -> rbuf
        if (lane == 0) {
            *(float4*)&rbuf[ib][w * 4] =
                make_float4(fast_tanh(A0), fast_tanh(A1), fast_tanh(A2), fast_tanh(A3));
        }

        // 2. retire the k(t+1) copy (issued at step t-1)
        if (w < 4) asm volatile("cp.async.wait_group 0;" ::: "memory");

        // 3. one barrier per step: publishes rbuf and ksm[(t+1)%3]
        __syncthreads();

        // 4. stage k(t+2) (slot safe: its old readers finished before the sync)
        if (w < 4) {
            const int t2 = (t + 2 < TT) ? t + 2 : TT - 1;
            uint32_t dst = (uint32_t)__cvta_generic_to_shared(&ksm[(t + 2) % 3][w * 128 + lane * 4]);
            const float* src = g_k + (size_t)t2 * BB * DD + (size_t)b * DD + w * 128 + lane * 4;
            asm volatile("cp.async.cg.shared.global [%0], [%1], 16;" :: "r"(dst), "l"(src) : "memory");
            asm volatile("cp.async.commit_group;" ::: "memory");
        }
        // prefetch wx/alpha(t+1)
        const int tn = (t < TT - 1) ? t + 1 : t;
        float wxn = __ldg(g_wx + (size_t)tn * BB * NN + b * NN + nv);
        float aln = __ldg(g_alpha + (size_t)tn * BB * NN + b * NN + nv);

        // 5. v-matvec: lane handles row grp over m in [m0, m0+8)
        float4 rA = *(const float4*)&rbuf[ib][m0];
        float4 rB = *(const float4*)&rbuf[ib][m0 + 4];
        float pv = dot4(rA, wrA) + dot4(rB, wrB);
        pv += __shfl_xor_sync(0xffffffffu, pv, 1);
        pv += __shfl_xor_sync(0xffffffffu, pv, 2);
        pv += __shfl_xor_sync(0xffffffffu, pv, 4);
        float v   = fast_tanh(pv + wxc);
        float c2v = (1.0f - alc) * v;
        if (gl == 0) g_c2[(size_t)t * BB * NN + b * NN + nv] = c2v;

        // broadcast c2/alpha for the warp's 4 rows; pack for f32x2
        ull c2p[4], alp[4];
#pragma unroll
        for (int i = 0; i < 4; i++) {
            float ci = __shfl_sync(0xffffffffu, c2v, i * 8 + gl);
            float ai = __shfl_sync(0xffffffffu, alc, i * 8 + gl);
            c2p[i] = pack2(ci, ci);
            alp[i] = pack2(ai, ai);
        }

        // 6. fused packed update + next-step dot
        const ull* kt = (const ull*)&ksm[t % 3][lane * 16];
        const ull* kn = (const ull*)&ksm[(t + 1) % 3][lane * 16];
        ull a0 = 0ull, a1 = 0ull, a2 = 0ull, a3 = 0ull;
#pragma unroll
        for (int c = 0; c < 8; c++) {
            ull k2c  = kt[c];
            ull kn2c = kn[c];
            ull u0 = mul2(c2p[0], k2c); s2[0][c] = fma2(alp[0], s2[0][c], u0); a0 = fma2(s2[0][c], kn2c, a0);
            ull u1 = mul2(c2p[1], k2c); s2[1][c] = fma2(alp[1], s2[1][c], u1); a1 = fma2(s2[1][c], kn2c, a1);
            ull u2 = mul2(c2p[2], k2c); s2[2][c] = fma2(alp[2], s2[2][c], u2); a2 = fma2(s2[2][c], kn2c, a2);
            ull u3 = mul2(c2p[3], k2c); s2[3][c] = fma2(alp[3], s2[3][c], u3); a3 = fma2(s2[3][c], kn2c, a3);
        }
        float2 f0 = unpack2(a0), f1 = unpack2(a1), f2 = unpack2(a2), f3 = unpack2(a3);
        float t0 = f0.x + f0.y, t1 = f1.x + f1.y, t2v = f2.x + f2.y, t3 = f3.x + f3.y;
#pragma unroll
        for (int off = 16; off >= 1; off >>= 1) {
            t0  += __shfl_xor_sync(0xffffffffu, t0, off);
            t1  += __shfl_xor_sync(0xffffffffu, t1, off);
            t2v += __shfl_xor_sync(0xffffffffu, t2v, off);
            t3  += __shfl_xor_sync(0xffffffffu, t3, off);
        }
        A0 = t0; A1 = t1; A2 = t2v; A3 = t3;

        wxc = wxn; alc = aln;
    }
}

// ============================================================================
// Kernel 3: parallel scan — replay S and compute y across all SMs.
// One warp per (b, n): lane owns 16 d's. DRAM-write-bound (~537 MB).
// ============================================================================
__global__ void __launch_bounds__(128) scan_kernel(
    const float* __restrict__ S0, float* __restrict__ out)
{
    const int gw   = blockIdx.x * 4 + (threadIdx.x >> 5);  // 0..511
    const int lane = threadIdx.x & 31;
    const int b    = gw >> 6;
    const int n    = gw & 63;

    float* out_y = out;                            // [T,B,N]
    float* out_S = out + (size_t)TT * BB * NN;     // [T+1,B,N,D]

    float4 s0_, s1_, s2_, s3_;
    {
        const float4* p = (const float4*)(S0 + (size_t)(b * NN + n) * DD + lane * 16);
        s0_ = p[0]; s1_ = p[1]; s2_ = p[2]; s3_ = p[3];
        float4* o = (float4*)(out_S + (size_t)(b * NN + n) * DD + lane * 16);
        o[0] = s0_; o[1] = s1_; o[2] = s2_; o[3] = s3_;
    }

    const float* kp = g_k + b * DD + lane * 16;
    const float* qp = g_q + b * DD + lane * 16;
    const float* cp = g_c2 + b * NN + n;
    const float* ap = g_alpha + b * NN + n;
    float* yp = out_y + b * NN + n;
    float* sp = out_S + (size_t)((BB + b) * NN + n) * DD + lane * 16;

    float4 k0 = *(const float4*)(kp);     float4 k1 = *(const float4*)(kp + 4);
    float4 k2 = *(const float4*)(kp + 8); float4 k3 = *(const float4*)(kp + 12);
    float4 q0 = *(const float4*)(qp);     float4 q1 = *(const float4*)(qp + 4);
    float4 q2 = *(const float4*)(qp + 8); float4 q3 = *(const float4*)(qp + 12);
    float c2 = __ldg(cp);
    float al = __ldg(ap);

    for (int t = 0; t < TT; t++) {
        const int adv  = (t < TT - 1) ? BB * DD : 0;
        const int advn = (t < TT - 1) ? BB * NN : 0;
        float4 nk0 = *(const float4*)(kp + adv);     float4 nk1 = *(const float4*)(kp + adv + 4);
        float4 nk2 = *(const float4*)(kp + adv + 8); float4 nk3 = *(const float4*)(kp + adv + 12);
        float4 nq0 = *(const float4*)(qp + adv);     float4 nq1 = *(const float4*)(qp + adv + 4);
        float4 nq2 = *(const float4*)(qp + adv + 8); float4 nq3 = *(const float4*)(qp + adv + 12);
        float nc2 = __ldg(cp + advn);
        float nal = __ldg(ap + advn);

        s0_.x = fmaf(al, s0_.x, c2 * k0.x); s0_.y = fmaf(al, s0_.y, c2 * k0.y);
        s0_.z = fmaf(al, s0_.z, c2 * k0.z); s0_.w = fmaf(al, s0_.w, c2 * k0.w);
        s1_.x = fmaf(al, s1_.x, c2 * k1.x); s1_.y = fmaf(al, s1_.y, c2 * k1.y);
        s1_.z = fmaf(al, s1_.z, c2 * k1.z); s1_.w = fmaf(al, s1_.w, c2 * k1.w);
        s2_.x = fmaf(al, s2_.x, c2 * k2.x); s2_.y = fmaf(al, s2_.y, c2 * k2.y);
        s2_.z = fmaf(al, s2_.z, c2 * k2.z); s2_.w = fmaf(al, s2_.w, c2 * k2.w);
        s3_.x = fmaf(al, s3_.x, c2 * k3.x); s3_.y = fmaf(al, s3_.y, c2 * k3.y);
        s3_.z = fmaf(al, s3_.z, c2 * k3.z); s3_.w = fmaf(al, s3_.w, c2 * k3.w);

        __stcs((float4*)sp + 0, s0_);
        __stcs((float4*)sp + 1, s1_);
        __stcs((float4*)sp + 2, s2_);
        __stcs((float4*)sp + 3, s3_);

        float y = dot4(s0_, q0) + dot4(s1_, q1) + dot4(s2_, q2) + dot4(s3_, q3);
        y = warp_sum(y);
        if (lane == 0) *yp = fast_tanh(y);

        k0 = nk0; k1 = nk1; k2 = nk2; k3 = nk3;
        q0 = nq0; q1 = nq1; q2 = nq2; q3 = nq3;
        c2 = nc2; al = nal;
        kp += BB * DD; qp += BB * DD; cp += BB * NN; ap += BB * NN;
        yp += BB * NN; sp += (size_t)BB * NN * DD;
    }
}

// ============================================================================
// Launch: proj -> recur (serial, emits c2 only) -> scan (parallel, big output)
//   inputs: x, S0, W_k, W_q, W_x, W_r, b, W_alpha, b_alpha
//   output: concat( y[T,B,N], S[T+1,B,N,D] )  fp32
// ============================================================================
extern "C" void kernel_launch(void* const* d_in, const int* in_sizes, int n_in,
                              void* d_out, int out_size)
{
    const float* x   = (const float*)d_in[0];
    const float* S0  = (const float*)d_in[1];
    const float* Wk  = (const float*)d_in[2];
    const float* Wq  = (const float*)d_in[3];
    const float* Wx  = (const float*)d_in[4];
    const float* Wr  = (const float*)d_in[5];
    const float* bv  = (const float*)d_in[6];
    const float* Wa  = (const float*)d_in[7];
    const float* ba  = (const float*)d_in[8];
    float* out = (float*)d_out;

    dim3 pg(PM / TBM, PN / TBN);   // (32, 9)
    proj_kernel<<<pg, 256>>>(x, Wk, Wq, Wx, Wa, bv, ba);

    recur_kernel<<<BB, 512>>>(S0, Wr);

    scan_kernel<<<128, 128>>>(S0, out);
}

// round 17
// speedup vs baseline: 1.2758x; 1.2758x over previous
#include <cuda_runtime.h>
#include <cstdint>
#include <math.h>

// Problem constants
#define TT 512
#define BB 8
#define DD 512
#define NN 64
#define CC 64              // chunk length
#define NCH (TT / CC)      // 8 chunks

// Scratch (allocation-free rule: __device__ globals)
__device__ float g_k[TT * BB * DD];
__device__ float g_q[TT * BB * DD];
__device__ float g_wx[TT * BB * NN];         // W_x @ x + b
__device__ float g_alpha[TT * BB * NN];      // sigmoid(W_alpha @ x + b_alpha)
__device__ float g_c2[TT * BB * NN];         // (1-alpha)*v
__device__ float g_S[BB * NN * DD];          // chunk-start state
__device__ float g_P[BB * CC * NN];          // P[b][tau][n]  = S_c . k_{t0+tau}
__device__ float g_Pq[BB * CC * NN];         // Pq[b][tau][n] = S_c . q_{t0+tau}
__device__ float g_G[BB * NCH * CC * CC];    // G[b][c][t][j]  = k_j . k_t   (local idx)
__device__ float g_Gq[BB * NCH * CC * CC];   // Gq[b][c][t][j] = k_j . q_t

// ---------------------------------------------------------------------------
__device__ __forceinline__ float fast_tanh(float x) {
    float e;
    asm("ex2.approx.f32 %0, %1;" : "=f"(e) : "f"(x * 2.8853900817779268f));
    float r;
    asm("rcp.approx.f32 %0, %1;" : "=f"(r) : "f"(e + 1.0f));
    return fmaf(-2.0f, r, 1.0f);
}
__device__ __forceinline__ float warp_sum(float v) {
    v += __shfl_xor_sync(0xffffffffu, v, 16);
    v += __shfl_xor_sync(0xffffffffu, v, 8);
    v += __shfl_xor_sync(0xffffffffu, v, 4);
    v += __shfl_xor_sync(0xffffffffu, v, 2);
    v += __shfl_xor_sync(0xffffffffu, v, 1);
    return v;
}
__device__ __forceinline__ float dot4(const float4 a, const float4 b) {
    return fmaf(a.x, b.x, fmaf(a.y, b.y, fmaf(a.z, b.z, a.w * b.w)));
}

// ============================================================================
// Kernel 1: fused projection GEMM (unchanged — passing, ~116us)
// ============================================================================
#define PM 4096
#define PK 512
#define PN 1152
#define TBM 128
#define TBN 128
#define TBK 16

__global__ __launch_bounds__(256) void proj_kernel(
    const float* __restrict__ x,
    const float* __restrict__ Wk, const float* __restrict__ Wq,
    const float* __restrict__ Wx, const float* __restrict__ Wa,
    const float* __restrict__ bvec, const float* __restrict__ ba)
{
    __shared__ __align__(16) float As[TBK][TBM + 4];
    __shared__ __align__(16) float Bs[TBK][TBN + 4];

    const int tid = threadIdx.x;
    const int tx = tid & 15;
    const int ty = tid >> 4;
    const int m0 = blockIdx.x * TBM;
    const int n0 = blockIdx.y * TBN;

    const int kq = tid & 3;
    const int r0 = tid >> 2;

    const float* wr0p;
    const float* wr1p;
    {
        int jg = n0 + r0;
        wr0p = (jg < 512) ? Wk + (size_t)jg * 512
             : (jg < 1024) ? Wq + (size_t)(jg - 512) * 512
             : (jg < 1088) ? Wx + (size_t)(jg - 1024) * 512
                           : Wa + (size_t)(jg - 1088) * 512;
        jg = n0 + r0 + 64;
        wr1p = (jg < 512) ? Wk + (size_t)jg * 512
             : (jg < 1024) ? Wq + (size_t)(jg - 512) * 512
             : (jg < 1088) ? Wx + (size_t)(jg - 1024) * 512
                           : Wa + (size_t)(jg - 1088) * 512;
    }
    const float* xr0 = x + (size_t)(m0 + r0) * PK;
    const float* xr1 = x + (size_t)(m0 + r0 + 64) * PK;

    float acc[8][8];
#pragma unroll
    for (int i = 0; i < 8; i++)
#pragma unroll
        for (int j = 0; j < 8; j++) acc[i][j] = 0.0f;

    for (int kt = 0; kt < PK; kt += TBK) {
        float4 a0 = *(const float4*)(xr0 + kt + kq * 4);
        float4 a1 = *(const float4*)(xr1 + kt + kq * 4);
        float4 b0 = *(const float4*)(wr0p + kt + kq * 4);
        float4 b1 = *(const float4*)(wr1p + kt + kq * 4);

        As[kq * 4 + 0][r0] = a0.x; As[kq * 4 + 1][r0] = a0.y;
        As[kq * 4 + 2][r0] = a0.z; As[kq * 4 + 3][r0] = a0.w;
        As[kq * 4 + 0][r0 + 64] = a1.x; As[kq * 4 + 1][r0 + 64] = a1.y;
        As[kq * 4 + 2][r0 + 64] = a1.z; As[kq * 4 + 3][r0 + 64] = a1.w;

        Bs[kq * 4 + 0][r0] = b0.x; Bs[kq * 4 + 1][r0] = b0.y;
        Bs[kq * 4 + 2][r0] = b0.z; Bs[kq * 4 + 3][r0] = b0.w;
        Bs[kq * 4 + 0][r0 + 64] = b1.x; Bs[kq * 4 + 1][r0 + 64] = b1.y;
        Bs[kq * 4 + 2][r0 + 64] = b1.z; Bs[kq * 4 + 3][r0 + 64] = b1.w;

        __syncthreads();

#pragma unroll
        for (int kk = 0; kk < TBK; kk++) {
            float a[8], bq[8];
            *(float4*)&a[0]  = *(const float4*)&As[kk][ty * 8];
            *(float4*)&a[4]  = *(const float4*)&As[kk][ty * 8 + 4];
            *(float4*)&bq[0] = *(const float4*)&Bs[kk][tx * 8];
            *(float4*)&bq[4] = *(const float4*)&Bs[kk][tx * 8 + 4];
#pragma unroll
            for (int i = 0; i < 8; i++)
#pragma unroll
                for (int j = 0; j < 8; j++)
                    acc[i][j] = fmaf(a[i], bq[j], acc[i][j]);
        }
        __syncthreads();
    }

    const int c0 = n0 + tx * 8;
    if (c0 < 512) {
#pragma unroll
        for (int i = 0; i < 8; i++) {
            int r = m0 + ty * 8 + i;
            float* base = g_k + (size_t)r * DD + c0;
            *(float4*)(base)     = make_float4(acc[i][0], acc[i][1], acc[i][2], acc[i][3]);
            *(float4*)(base + 4) = make_float4(acc[i][4], acc[i][5], acc[i][6], acc[i][7]);
        }
    } else if (c0 < 1024) {
#pragma unroll
        for (int i = 0; i < 8; i++) {
            int r = m0 + ty * 8 + i;
            float* base = g_q + (size_t)r * DD + (c0 - 512);
            *(float4*)(base)     = make_float4(acc[i][0], acc[i][1], acc[i][2], acc[i][3]);
            *(float4*)(base + 4) = make_float4(acc[i][4], acc[i][5], acc[i][6], acc[i][7]);
        }
    } else if (c0 < 1088) {
        const int cc = c0 - 1024;
        float bb[8];
#pragma unroll
        for (int j = 0; j < 8; j++) bb[j] = bvec[cc + j];
#pragma unroll
        for (int i = 0; i < 8; i++) {
            int r = m0 + ty * 8 + i;
            float* base = g_wx + (size_t)r * NN + cc;
#pragma unroll
            for (int j = 0; j < 8; j++) base[j] = acc[i][j] + bb[j];
        }
    } else {
        const int cc = c0 - 1088;
        float bb[8];
#pragma unroll
        for (int j = 0; j < 8; j++) bb[j] = ba[cc + j];
#pragma unroll
        for (int i = 0; i < 8; i++) {
            int r = m0 + ty * 8 + i;
            float* base = g_alpha + (size_t)r * NN + cc;
#pragma unroll
            for (int j = 0; j < 8; j++)
                base[j] = 1.0f / (1.0f + expf(-(acc[i][j] + bb[j])));
        }
    }
}

// ============================================================================
// Kernel 2: per-chunk Gram matrices (parallel, upfront).
// blockIdx.x = b*NCH + c;  blockIdx.y: 0 -> G (rows=k), 1 -> Gq (rows=q)
// Out[t][j] = Row_t . k_j   (local t, j in chunk)
// NOTE: tile row stride must be a multiple of 16B for the float4 reads —
// CC+4 = 68 floats = 272B = 17*16. (CC+1 was the R16 misalignment bug.)
// ============================================================================
__global__ __launch_bounds__(256) void gram_kernel()
{
    const int b = blockIdx.x >> 3;
    const int c = blockIdx.x & 7;
    const int isq = blockIdx.y;
    const float* Bsrc = isq ? g_q : g_k;
    float* outp = (isq ? g_Gq : g_G) + (size_t)(b * NCH + c) * CC * CC;

    __shared__ __align__(16) float As[32][CC + 4];   // As[dd][j] = k_j[kt+dd]
    __shared__ __align__(16) float Bs[32][CC + 4];   // Bs[dd][t] = Row_t[kt+dd]

    const int tid = threadIdx.x;
    const int tx = tid & 15;   // j tile (4 cols)
    const int ty = tid >> 4;   // t tile (4 rows)

    float acc[4][4];
#pragma unroll
    for (int i = 0; i < 4; i++)
#pragma unroll
        for (int j = 0; j < 4; j++) acc[i][j] = 0.0f;

    const int t0 = c * CC;

    for (int kt = 0; kt < DD; kt += 32) {
#pragma unroll
        for (int u = 0; u < 2; u++) {
            int f4 = tid * 2 + u;          // 0..511
            int row = f4 >> 3;             // 0..63
            int col4 = f4 & 7;             // 0..7
            const float* ap = g_k + ((size_t)(t0 + row) * BB + b) * DD + kt + col4 * 4;
            const float* bp = Bsrc + ((size_t)(t0 + row) * BB + b) * DD + kt + col4 * 4;
            float4 av = *(const float4*)ap;
            float4 bv = *(const float4*)bp;
            As[col4 * 4 + 0][row] = av.x; As[col4 * 4 + 1][row] = av.y;
            As[col4 * 4 + 2][row] = av.z; As[col4 * 4 + 3][row] = av.w;
            Bs[col4 * 4 + 0][row] = bv.x; Bs[col4 * 4 + 1][row] = bv.y;
            Bs[col4 * 4 + 2][row] = bv.z; Bs[col4 * 4 + 3][row] = bv.w;
        }
        __syncthreads();

#pragma unroll
        for (int dd = 0; dd < 32; dd++) {
            float aj[4], bt[4];
            *(float4*)aj = *(const float4*)&As[dd][tx * 4];
            *(float4*)bt = *(const float4*)&Bs[dd][ty * 4];
#pragma unroll
            for (int i = 0; i < 4; i++)
#pragma unroll
                for (int j = 0; j < 4; j++)
                    acc[i][j] = fmaf(bt[i], aj[j], acc[i][j]);
        }
        __syncthreads();
    }

#pragma unroll
    for (int i = 0; i < 4; i++) {
        int t = ty * 4 + i;
        *(float4*)(outp + t * CC + tx * 4) =
            make_float4(acc[i][0], acc[i][1], acc[i][2], acc[i][3]);
    }
}

// ---------------------------------------------------------------------------
// P/Pq computation for chunk `cn` from state slices in registers (warp-level)
// ---------------------------------------------------------------------------
__device__ __forceinline__ void compute_P(
    int cn, int b, int n, int lane,
    float4 s0_, float4 s1_, float4 s2_, float4 s3_)
{
    const int tbase = cn * CC;
    for (int tau = 0; tau < CC; tau++) {
        const float* kp = g_k + ((size_t)(tbase + tau) * BB + b) * DD + lane * 16;
        const float* qp = g_q + ((size_t)(tbase + tau) * BB + b) * DD + lane * 16;
        float4 k0 = *(const float4*)(kp);     float4 k1 = *(const float4*)(kp + 4);
        float4 k2 = *(const float4*)(kp + 8); float4 k3 = *(const float4*)(kp + 12);
        float4 q0 = *(const float4*)(qp);     float4 q1 = *(const float4*)(qp + 4);
        float4 q2 = *(const float4*)(qp + 8); float4 q3 = *(const float4*)(qp + 12);
        float p  = dot4(s0_, k0) + dot4(s1_, k1) + dot4(s2_, k2) + dot4(s3_, k3);
        float pq = dot4(s0_, q0) + dot4(s1_, q1) + dot4(s2_, q2) + dot4(s3_, q3);
        p = warp_sum(p); pq = warp_sum(pq);
        if (lane == 0) {
            g_P [b * CC * NN + tau * NN + n] = p;
            g_Pq[b * CC * NN + tau * NN + n] = pq;
        }
    }
}

// ============================================================================
// Kernel 3: init — write S[0], seed g_S = S0, compute P/Pq for chunk 0.
// One warp per (b, n).
// ============================================================================
__global__ __launch_bounds__(128) void init_kernel(
    const float* __restrict__ S0, float* __restrict__ out)
{
    const int gw   = blockIdx.x * 4 + (threadIdx.x >> 5);
    const int lane = threadIdx.x & 31;
    const int b    = gw >> 6;
    const int n    = gw & 63;

    float* out_S = out + (size_t)TT * BB * NN;

    const float4* p = (const float4*)(S0 + (size_t)(b * NN + n) * DD + lane * 16);
    float4 s0_ = p[0], s1_ = p[1], s2_ = p[2], s3_ = p[3];

    float4* o = (float4*)(out_S + (size_t)(b * NN + n) * DD + lane * 16);
    o[0] = s0_; o[1] = s1_; o[2] = s2_; o[3] = s3_;
    float4* gs = (float4*)(g_S + (size_t)(b * NN + n) * DD + lane * 16);
    gs[0] = s0_; gs[1] = s1_; gs[2] = s2_; gs[3] = s3_;

    compute_P(0, b, n, lane, s0_, s1_, s2_, s3_);
}

// ============================================================================
// Kernel 4: serial recurrence for one chunk — N-dim space only.
// 8 CTAs (one per batch) x 256 threads; thread: n = tid>>2, quarter qd = tid&3
// handling j in [qd*16, qd*16+16). State: u[16] regs + D. One bar/step.
// Emits y (direct to out) and c2 (for chunkscan).
// ============================================================================
__global__ __launch_bounds__(256, 1) void serial_kernel(
    int c, const float* __restrict__ Wr, float* __restrict__ out)
{
    const int b   = blockIdx.x;
    const int tid = threadIdx.x;
    const int n   = tid >> 2;
    const int qd  = tid & 3;
    const int jb  = qd * 16;

    __shared__ __align__(16) float sG[CC * CC];    // [t][j]
    __shared__ __align__(16) float sGq[CC * CC];
    __shared__ __align__(16) float rbuf[2][NN];

    // load Gram blocks (coalesced float4)
    {
        const float4* gsrc  = (const float4*)(g_G  + (size_t)(b * NCH + c) * CC * CC);
        const float4* gqsrc = (const float4*)(g_Gq + (size_t)(b * NCH + c) * CC * CC);
        float4* dG  = (float4*)sG;
        float4* dGq = (float4*)sGq;
#pragma unroll
        for (int i = 0; i < 4; i++) {
            dG [tid + 256 * i] = gsrc [tid + 256 * i];
            dGq[tid + 256 * i] = gqsrc[tid + 256 * i];
        }
    }

    // W_r fragment: Wr[n][jb..jb+16)
    float4 w0 = *(const float4*)(Wr + n * NN + jb);
    float4 w1 = *(const float4*)(Wr + n * NN + jb + 4);
    float4 w2 = *(const float4*)(Wr + n * NN + jb + 8);
    float4 w3 = *(const float4*)(Wr + n * NN + jb + 12);

    float u[16];
#pragma unroll
    for (int i = 0; i < 16; i++) u[i] = 0.0f;
    float D = 1.0f;

    const int t0 = c * CC;
    const int sofs = b * NN + n;

    float Pc  = __ldg(g_P  + b * CC * NN + 0 * NN + n);
    float Pqc = __ldg(g_Pq + b * CC * NN + 0 * NN + n);
    float wxc = __ldg(g_wx + (size_t)t0 * BB * NN + sofs);
    float alc = __ldg(g_alpha + (size_t)t0 * BB * NN + sofs);

    __syncthreads();   // Gram blocks visible

    for (int tau = 0; tau < CC; tau++) {
        const int t = t0 + tau;

        // ---- A = D*P + sum_{j<tau} u_j * G[tau][j] ----
        const float4* gt = (const float4*)&sG[tau * CC + jb];
        float4 g0 = gt[0], g1 = gt[1], g2 = gt[2], g3 = gt[3];
        float a0 = fmaf(u[0], g0.x, fmaf(u[1], g0.y, fmaf(u[2],  g0.z, u[3]  * g0.w)));
        float a1 = fmaf(u[4], g1.x, fmaf(u[5], g1.y, fmaf(u[6],  g1.z, u[7]  * g1.w)));
        float a2 = fmaf(u[8], g2.x, fmaf(u[9], g2.y, fmaf(u[10], g2.z, u[11] * g2.w)));
        float a3 = fmaf(u[12],g3.x, fmaf(u[13],g3.y, fmaf(u[14], g3.z, u[15] * g3.w)));
        float a = (a0 + a1) + (a2 + a3);
        a += __shfl_xor_sync(0xffffffffu, a, 1);
        a += __shfl_xor_sync(0xffffffffu, a, 2);
        a = fmaf(D, Pc, a);

        float rv = fast_tanh(a);
        if (qd == 0) rbuf[tau & 1][n] = rv;
        __syncthreads();

        // prefetch next-step scalars
        const int taun = (tau < CC - 1) ? tau + 1 : tau;
        const int tn   = t0 + taun;
        float Pn  = __ldg(g_P  + b * CC * NN + taun * NN + n);
        float Pqn = __ldg(g_Pq + b * CC * NN + taun * NN + n);
        float wxn = __ldg(g_wx + (size_t)tn * BB * NN + sofs);
        float aln = __ldg(g_alpha + (size_t)tn * BB * NN + sofs);

        // ---- v = tanh(W_r r + wx); c2 = (1-al)*v ----
        const float4* rr = (const float4*)&rbuf[tau & 1][jb];
        float4 r0 = rr[0], r1 = rr[1], r2 = rr[2], r3 = rr[3];
        float pv = dot4(r0, w0) + dot4(r1, w1) + dot4(r2, w2) + dot4(r3, w3);
        pv += __shfl_xor_sync(0xffffffffu, pv, 1);
        pv += __shfl_xor_sync(0xffffffffu, pv, 2);
        float v  = fast_tanh(pv + wxc);
        float c2 = (1.0f - alc) * v;

        // ---- state update: u_j *= al ; u_tau = c2 ; D *= al ----
#pragma unroll
        for (int i = 0; i < 16; i++) {
            float un = u[i] * alc;
            u[i] = (jb + i == tau) ? c2 : un;
        }
        D *= alc;

        // ---- Y = D*Pq + sum_{j<=tau} u_j * Gq[tau][j] ; y = tanh(Y) ----
        const float4* gqt = (const float4*)&sGq[tau * CC + jb];
        float4 h0 = gqt[0], h1 = gqt[1], h2 = gqt[2], h3 = gqt[3];
        float y0 = fmaf(u[0], h0.x, fmaf(u[1], h0.y, fmaf(u[2],  h0.z, u[3]  * h0.w)));
        float y1 = fmaf(u[4], h1.x, fmaf(u[5], h1.y, fmaf(u[6],  h1.z, u[7]  * h1.w)));
        float y2 = fmaf(u[8], h2.x, fmaf(u[9], h2.y, fmaf(u[10], h2.z, u[11] * h2.w)));
        float y3 = fmaf(u[12],h3.x, fmaf(u[13],h3.y, fmaf(u[14], h3.z, u[15] * h3.w)));
        float Y = (y0 + y1) + (y2 + y3);
        Y += __shfl_xor_sync(0xffffffffu, Y, 1);
        Y += __shfl_xor_sync(0xffffffffu, Y, 2);
        Y = fmaf(D, Pqc, Y);

        if (qd == 0) {
            out [(size_t)t * BB * NN + sofs] = fast_tanh(Y);   // y[t,b,n]
            g_c2[(size_t)t * BB * NN + sofs] = c2;
        }

        Pc = Pn; Pqc = Pqn; wxc = wxn; alc = aln;
    }
}

// ============================================================================
// Kernel 5: chunkscan — replay S over chunk c (wide), write S to out,
// advance g_S, compute P/Pq for chunk c+1. One warp per (b, n).
// ============================================================================
__global__ __launch_bounds__(128) void chunkscan_kernel(int c, float* __restrict__ out)
{
    const int gw   = blockIdx.x * 4 + (threadIdx.x >> 5);
    const int lane = threadIdx.x & 31;
    const int b    = gw >> 6;
    const int n    = gw & 63;

    float* out_S = out + (size_t)TT * BB * NN;

    float4* gs = (float4*)(g_S + (size_t)(b * NN + n) * DD + lane * 16);
    float4 s0_ = gs[0], s1_ = gs[1], s2_ = gs[2], s3_ = gs[3];

    const int t0 = c * CC;
    for (int tau = 0; tau < CC; tau++) {
        const int t = t0 + tau;
        float al = __ldg(g_alpha + (size_t)t * BB * NN + b * NN + n);
        float c2 = __ldg(g_c2    + (size_t)t * BB * NN + b * NN + n);
        const float* kp = g_k + ((size_t)t * BB + b) * DD + lane * 16;
        float4 k0 = *(const float4*)(kp);     float4 k1 = *(const float4*)(kp + 4);
        float4 k2 = *(const float4*)(kp + 8); float4 k3 = *(const float4*)(kp + 12);

        s0_.x = fmaf(al, s0_.x, c2 * k0.x); s0_.y = fmaf(al, s0_.y, c2 * k0.y);
        s0_.z = fmaf(al, s0_.z, c2 * k0.z); s0_.w = fmaf(al, s0_.w, c2 * k0.w);
        s1_.x = fmaf(al, s1_.x, c2 * k1.x); s1_.y = fmaf(al, s1_.y, c2 * k1.y);
        s1_.z = fmaf(al, s1_.z, c2 * k1.z); s1_.w = fmaf(al, s1_.w, c2 * k1.w);
        s2_.x = fmaf(al, s2_.x, c2 * k2.x); s2_.y = fmaf(al, s2_.y, c2 * k2.y);
        s2_.z = fmaf(al, s2_.z, c2 * k2.z); s2_.w = fmaf(al, s2_.w, c2 * k2.w);
        s3_.x = fmaf(al, s3_.x, c2 * k3.x); s3_.y = fmaf(al, s3_.y, c2 * k3.y);
        s3_.z = fmaf(al, s3_.z, c2 * k3.z); s3_.w = fmaf(al, s3_.w, c2 * k3.w);

        float4* sp = (float4*)(out_S + ((size_t)(t + 1) * BB * NN + b * NN + n) * DD + lane * 16);
        __stcs(sp + 0, s0_); __stcs(sp + 1, s1_);
        __stcs(sp + 2, s2_); __stcs(sp + 3, s3_);
    }

    gs[0] = s0_; gs[1] = s1_; gs[2] = s2_; gs[3] = s3_;

    if (c < NCH - 1)
        compute_P(c + 1, b, n, lane, s0_, s1_, s2_, s3_);
}

// ============================================================================
// Launch: proj -> gram -> init -> 8 x (serial(c) -> chunkscan(c))
//   inputs: x, S0, W_k, W_q, W_x, W_r, b, W_alpha, b_alpha
//   output: concat( y[T,B,N], S[T+1,B,N,D] )  fp32
// ============================================================================
extern "C" void kernel_launch(void* const* d_in, const int* in_sizes, int n_in,
                              void* d_out, int out_size)
{
    const float* x   = (const float*)d_in[0];
    const float* S0  = (const float*)d_in[1];
    const float* Wk  = (const float*)d_in[2];
    const float* Wq  = (const float*)d_in[3];
    const float* Wx  = (const float*)d_in[4];
    const float* Wr  = (const float*)d_in[5];
    const float* bv  = (const float*)d_in[6];
    const float* Wa  = (const float*)d_in[7];
    const float* ba  = (const float*)d_in[8];
    float* out = (float*)d_out;

    dim3 pg(PM / TBM, PN / TBN);   // (32, 9)
    proj_kernel<<<pg, 256>>>(x, Wk, Wq, Wx, Wa, bv, ba);

    gram_kernel<<<dim3(BB * NCH, 2), 256>>>();
    init_kernel<<<128, 128>>>(S0, out);

    for (int c = 0; c < NCH; c++) {
        serial_kernel<<<BB, 256>>>(c, Wr, out);
        chunkscan_kernel<<<128, 128>>>(c, out);
    }
}